// round 2
// baseline (speedup 1.0000x reference)
#include <cuda_runtime.h>
#include <cuda_bf16.h>

// Problem constants (fixed by reference)
#define N_NODES 50000
#define EMB 128
#define N_EDGES 600000
#define NLAYER 5
#define BN_EPS 1e-5f

// ---------------- device scratch (no allocations allowed) ----------------
__device__ float g_h[N_NODES * EMB];        // node features (layer input)
__device__ float g_agg[N_NODES * EMB];      // scatter-add accumulator
__device__ float g_hidden[N_NODES * 2 * EMB]; // MLP hidden (relu(agg@W1+b1))
__device__ float g_h2[N_NODES * EMB];       // MLP output pre-BN
__device__ float g_sums[2 * EMB];           // [0:128) col sums, [128:256) col sumsq
__device__ float g_scale[EMB];              // BN scale  = gamma * rsqrt(var+eps)
__device__ float g_shift[EMB];              // BN shift  = beta - mu*scale

// ---------------- helpers ----------------
__device__ __forceinline__ void red_add_v4(float* p, float4 v) {
    asm volatile("red.global.add.v4.f32 [%0], {%1,%2,%3,%4};"
                 :: "l"(p), "f"(v.x), "f"(v.y), "f"(v.z), "f"(v.w) : "memory");
}

// ---------------- kernels ----------------

// h[i] = atom_emb[x[i,0]] + chir_emb[x[i,1]] + hyb_emb[x[i,2]]
// one warp-lane handles 4 consecutive features (float4); 32 lanes/node
__global__ __launch_bounds__(256)
void embed_kernel(const int* __restrict__ x,
                  const float4* __restrict__ atom,
                  const float4* __restrict__ chir,
                  const float4* __restrict__ hyb,
                  float4* __restrict__ h) {
    int t = blockIdx.x * blockDim.x + threadIdx.x;
    if (t >= N_NODES * 32) return;
    int node = t >> 5, lane = t & 31;
    int a  = x[3 * node + 0];
    int c  = x[3 * node + 1];
    int hy = x[3 * node + 2];
    float4 o  = atom[a * 32 + lane];
    float4 c4 = chir[c * 32 + lane];
    float4 h4 = hyb[hy * 32 + lane];
    o.x += c4.x + h4.x; o.y += c4.y + h4.y;
    o.z += c4.z + h4.z; o.w += c4.w + h4.w;
    h[t] = o;
}

__global__ __launch_bounds__(256)
void zero_kernel(float4* __restrict__ agg, float* __restrict__ sums) {
    int t = blockIdx.x * blockDim.x + threadIdx.x;
    if (t < N_NODES * 32) agg[t] = make_float4(0.f, 0.f, 0.f, 0.f);
    if (t < 2 * EMB) sums[t] = 0.f;
}

// one warp per edge: agg[dst] += h[src] + e1[ea0] + e2[ea1]
__global__ __launch_bounds__(256)
void scatter_kernel(const float4* __restrict__ h,
                    const int* __restrict__ ei,   // [2, E]
                    const int* __restrict__ ea,   // [E, 2]
                    const float4* __restrict__ e1l,
                    const float4* __restrict__ e2l,
                    float* __restrict__ agg) {
    int t = blockIdx.x * blockDim.x + threadIdx.x;
    int e = t >> 5, lane = t & 31;
    if (e >= N_EDGES) return;
    int src = ei[e];
    int dst = ei[N_EDGES + e];
    int a0 = ea[2 * e], a1 = ea[2 * e + 1];
    float4 v  = h[src * 32 + lane];
    float4 x1 = e1l[a0 * 32 + lane];
    float4 x2 = e2l[a1 * 32 + lane];
    v.x += x1.x + x2.x; v.y += x1.y + x2.y;
    v.z += x1.z + x2.z; v.w += x1.w + x2.w;
    red_add_v4(agg + (size_t)dst * EMB + lane * 4, v);
}

// Tiled SGEMM: C[M,N] = A[M,K] @ B[K,N] + bias, optional ReLU, optional
// per-column sum/sumsq accumulation (for BN stats) fused in epilogue.
// Block tile 64x64, BK=16, 256 threads, 4x4 microtile per thread.
template<int K, int N, bool RELU, bool STATS>
__global__ __launch_bounds__(256)
void gemm64(const float* __restrict__ A, const float* __restrict__ B,
            const float* __restrict__ bias, float* __restrict__ C,
            int M, float* __restrict__ sums) {
    __shared__ float As[16][64];   // transposed: As[k][row]
    __shared__ float Bs[16][64];
    __shared__ float sS[64];
    __shared__ float sQ[64];

    const int tid = threadIdx.x;
    const int tx = tid & 15;        // column group (4 cols)
    const int ty = tid >> 4;        // row group (4 rows)
    const int row0 = blockIdx.x * 64;
    const int col0 = blockIdx.y * 64;

    if (STATS && tid < 64) { sS[tid] = 0.f; sQ[tid] = 0.f; }

    const int ar = tid >> 2;          // 0..63
    const int ac = (tid & 3) * 4;     // 0..12
    const int br = tid >> 4;          // 0..15
    const int bc = (tid & 15) * 4;    // 0..60

    float acc[4][4] = {};

    for (int k0 = 0; k0 < K; k0 += 16) {
        float4 av = make_float4(0.f, 0.f, 0.f, 0.f);
        if (row0 + ar < M)
            av = *(const float4*)(A + (size_t)(row0 + ar) * K + k0 + ac);
        As[ac + 0][ar] = av.x;
        As[ac + 1][ar] = av.y;
        As[ac + 2][ar] = av.z;
        As[ac + 3][ar] = av.w;
        *(float4*)&Bs[br][bc] = *(const float4*)(B + (size_t)(k0 + br) * N + col0 + bc);
        __syncthreads();
#pragma unroll
        for (int k = 0; k < 16; k++) {
            float4 a4 = *(const float4*)&As[k][ty * 4];
            float4 b4 = *(const float4*)&Bs[k][tx * 4];
            float ra[4] = {a4.x, a4.y, a4.z, a4.w};
            float rb[4] = {b4.x, b4.y, b4.z, b4.w};
#pragma unroll
            for (int m = 0; m < 4; m++)
#pragma unroll
                for (int n = 0; n < 4; n++)
                    acc[m][n] = fmaf(ra[m], rb[n], acc[m][n]);
        }
        __syncthreads();
    }

    // epilogue: bias (+relu), store, optional stats
    float bv[4];
#pragma unroll
    for (int n = 0; n < 4; n++) bv[n] = bias[col0 + tx * 4 + n];

    float cv[4][4];
#pragma unroll
    for (int m = 0; m < 4; m++) {
        int r = row0 + ty * 4 + m;
        if (r < M) {
#pragma unroll
            for (int n = 0; n < 4; n++) {
                float c = acc[m][n] + bv[n];
                if (RELU) c = fmaxf(c, 0.f);
                cv[m][n] = c;
            }
            float4 o = make_float4(cv[m][0], cv[m][1], cv[m][2], cv[m][3]);
            *(float4*)(C + (size_t)r * N + col0 + tx * 4) = o;
        } else {
#pragma unroll
            for (int n = 0; n < 4; n++) cv[m][n] = 0.f;
        }
    }

    if (STATS) {
#pragma unroll
        for (int n = 0; n < 4; n++) {
            float ps = 0.f, pq = 0.f;
#pragma unroll
            for (int m = 0; m < 4; m++) {
                int r = row0 + ty * 4 + m;
                if (r < M) { ps += cv[m][n]; pq += cv[m][n] * cv[m][n]; }
            }
            atomicAdd(&sS[tx * 4 + n], ps);
            atomicAdd(&sQ[tx * 4 + n], pq);
        }
        __syncthreads();
        if (tid < 64) {
            atomicAdd(&sums[col0 + tid], sS[tid]);
            atomicAdd(&sums[EMB + col0 + tid], sQ[tid]);
        }
    }
}

// compute BN scale/shift from accumulated sums
__global__ void bn_prep(const float* __restrict__ sums,
                        const float* __restrict__ gamma,
                        const float* __restrict__ beta,
                        float* __restrict__ scale,
                        float* __restrict__ shift) {
    int c = threadIdx.x;
    if (c >= EMB) return;
    const float inv_n = 1.0f / (float)N_NODES;
    float mu  = sums[c] * inv_n;
    float var = sums[EMB + c] * inv_n - mu * mu;
    float rs  = rsqrtf(var + BN_EPS);
    float sc  = gamma[c] * rs;
    scale[c] = sc;
    shift[c] = beta[c] - mu * sc;
}

// out = h2 * scale + shift, optional ReLU
__global__ __launch_bounds__(256)
void bn_apply(const float4* __restrict__ h2, float4* __restrict__ out,
              const float4* __restrict__ scale, const float4* __restrict__ shift,
              int relu) {
    int t = blockIdx.x * blockDim.x + threadIdx.x;
    if (t >= N_NODES * 32) return;
    int lane = t & 31;
    float4 v  = h2[t];
    float4 sc = scale[lane];
    float4 sh = shift[lane];
    float4 o;
    o.x = fmaf(v.x, sc.x, sh.x);
    o.y = fmaf(v.y, sc.y, sh.y);
    o.z = fmaf(v.z, sc.z, sh.z);
    o.w = fmaf(v.w, sc.w, sh.w);
    if (relu) {
        o.x = fmaxf(o.x, 0.f); o.y = fmaxf(o.y, 0.f);
        o.z = fmaxf(o.z, 0.f); o.w = fmaxf(o.w, 0.f);
    }
    out[t] = o;
}

// ---------------- launch ----------------
extern "C" void kernel_launch(void* const* d_in, const int* in_sizes, int n_in,
                              void* d_out, int out_size) {
    const int*   x    = (const int*)  d_in[0];
    const int*   ei   = (const int*)  d_in[1];
    const int*   ea   = (const int*)  d_in[2];
    const float* atom = (const float*)d_in[3];
    const float* chir = (const float*)d_in[4];
    const float* hyb  = (const float*)d_in[5];
    const float* e1   = (const float*)d_in[6];  // [5,6,128]
    const float* e2   = (const float*)d_in[7];  // [5,4,128]
    const float* W1   = (const float*)d_in[8];  // [5,128,256]
    const float* b1   = (const float*)d_in[9];  // [5,256]
    const float* W2   = (const float*)d_in[10]; // [5,256,128]
    const float* b2   = (const float*)d_in[11]; // [5,128]
    const float* gamma= (const float*)d_in[12]; // [5,128]
    const float* beta = (const float*)d_in[13]; // [5,128]
    float* out = (float*)d_out;

    float *h, *agg, *hidden, *h2, *sums, *scale, *shift;
    cudaGetSymbolAddress((void**)&h,      g_h);
    cudaGetSymbolAddress((void**)&agg,    g_agg);
    cudaGetSymbolAddress((void**)&hidden, g_hidden);
    cudaGetSymbolAddress((void**)&h2,     g_h2);
    cudaGetSymbolAddress((void**)&sums,   g_sums);
    cudaGetSymbolAddress((void**)&scale,  g_scale);
    cudaGetSymbolAddress((void**)&shift,  g_shift);

    const int tpb = 256;
    const int node_grid = (N_NODES * 32) / tpb;       // 6250
    const int edge_grid = (N_EDGES * 32) / tpb;       // 75000
    const dim3 g1((N_NODES + 63) / 64, 256 / 64);     // GEMM1 grid (782,4)
    const dim3 g2((N_NODES + 63) / 64, 128 / 64);     // GEMM2 grid (782,2)

    embed_kernel<<<node_grid, tpb>>>(x, (const float4*)atom, (const float4*)chir,
                                     (const float4*)hyb, (float4*)h);

    for (int l = 0; l < NLAYER; l++) {
        zero_kernel<<<node_grid, tpb>>>((float4*)agg, sums);
        scatter_kernel<<<edge_grid, tpb>>>((const float4*)h, ei, ea,
                                           (const float4*)(e1 + (size_t)l * 6 * EMB),
                                           (const float4*)(e2 + (size_t)l * 4 * EMB),
                                           agg);
        gemm64<128, 256, true,  false><<<g1, tpb>>>(agg, W1 + (size_t)l * 128 * 256,
                                                    b1 + (size_t)l * 256, hidden,
                                                    N_NODES, nullptr);
        gemm64<256, 128, false, true ><<<g2, tpb>>>(hidden, W2 + (size_t)l * 256 * 128,
                                                    b2 + (size_t)l * 128, h2,
                                                    N_NODES, sums);
        bn_prep<<<1, 128>>>(sums, gamma + (size_t)l * EMB, beta + (size_t)l * EMB,
                            scale, shift);
        bn_apply<<<node_grid, tpb>>>((const float4*)h2,
                                     (l == NLAYER - 1) ? (float4*)out : (float4*)h,
                                     (const float4*)scale, (const float4*)shift,
                                     (l < NLAYER - 1) ? 1 : 0);
    }
}

// round 3
// speedup vs baseline: 1.1126x; 1.1126x over previous
#include <cuda_runtime.h>
#include <cuda_bf16.h>

#define N_NODES 50000
#define EMB 128
#define N_EDGES 600000
#define NLAYER 5
#define BN_EPS 1e-5f

// ---------------- device scratch ----------------
__device__ float g_h[N_NODES * EMB];
__device__ float g_agg[N_NODES * EMB];
__device__ float g_hidden[N_NODES * 2 * EMB];
__device__ float g_h2[N_NODES * EMB];
__device__ float g_sums[2 * EMB];
__device__ float g_scale[EMB];
__device__ float g_shift[EMB];
// CSR structures (built once per call; edges are layer-invariant)
__device__ int g_counts[N_NODES];
__device__ int g_cursor[N_NODES];
__device__ int g_rowptr[N_NODES + 1];
__device__ unsigned g_elist[N_EDGES];

// ---------------- f32x2 helpers ----------------
__device__ __forceinline__ unsigned long long pack2_dup(float a) {
    unsigned long long r;
    asm("mov.b64 %0, {%1,%1};" : "=l"(r) : "f"(a));
    return r;
}
__device__ __forceinline__ unsigned long long fma2(unsigned long long a,
                                                   unsigned long long b,
                                                   unsigned long long c) {
    unsigned long long d;
    asm("fma.rn.f32x2 %0, %1, %2, %3;" : "=l"(d) : "l"(a), "l"(b), "l"(c));
    return d;
}
__device__ __forceinline__ void unpack2(unsigned long long v, float& lo, float& hi) {
    asm("mov.b64 {%0,%1}, %2;" : "=f"(lo), "=f"(hi) : "l"(v));
}

// ---------------- embedding ----------------
__global__ __launch_bounds__(256)
void embed_kernel(const int* __restrict__ x,
                  const float4* __restrict__ atom,
                  const float4* __restrict__ chir,
                  const float4* __restrict__ hyb,
                  float4* __restrict__ h) {
    int t = blockIdx.x * blockDim.x + threadIdx.x;
    if (t >= N_NODES * 32) return;
    int node = t >> 5, lane = t & 31;
    int a  = x[3 * node + 0];
    int c  = x[3 * node + 1];
    int hy = x[3 * node + 2];
    float4 o  = atom[a * 32 + lane];
    float4 c4 = chir[c * 32 + lane];
    float4 h4 = hyb[hy * 32 + lane];
    o.x += c4.x + h4.x; o.y += c4.y + h4.y;
    o.z += c4.z + h4.z; o.w += c4.w + h4.w;
    h[t] = o;
}

// ---------------- CSR build (once per call) ----------------
__global__ __launch_bounds__(256)
void zero_counts(int* __restrict__ counts) {
    int t = blockIdx.x * blockDim.x + threadIdx.x;
    if (t < N_NODES) counts[t] = 0;
}

__global__ __launch_bounds__(256)
void hist_kernel(const int* __restrict__ ei, int* __restrict__ counts) {
    int e = blockIdx.x * blockDim.x + threadIdx.x;
    if (e < N_EDGES) atomicAdd(&counts[ei[N_EDGES + e]], 1);
}

// single-block exclusive scan over 50000 counts -> rowptr + cursor copy
__global__ __launch_bounds__(1024)
void scan_kernel(const int* __restrict__ counts, int* __restrict__ rowptr,
                 int* __restrict__ cursor) {
    __shared__ int part[1024];
    const int tid = threadIdx.x;
    const int CH = (N_NODES + 1023) / 1024;  // 49
    const int beg = tid * CH;
    int s = 0;
    for (int i = 0; i < CH; i++) {
        int idx = beg + i;
        if (idx < N_NODES) s += counts[idx];
    }
    part[tid] = s;
    __syncthreads();
    // Hillis-Steele inclusive scan
    for (int off = 1; off < 1024; off <<= 1) {
        int add = (tid >= off) ? part[tid - off] : 0;
        __syncthreads();
        part[tid] += add;
        __syncthreads();
    }
    int run = (tid > 0) ? part[tid - 1] : 0;
    for (int i = 0; i < CH; i++) {
        int idx = beg + i;
        if (idx < N_NODES) {
            int c = counts[idx];
            rowptr[idx] = run;
            cursor[idx] = run;
            run += c;
        }
    }
    if (tid == 1023) rowptr[N_NODES] = part[1023];
}

__global__ __launch_bounds__(256)
void fill_kernel(const int* __restrict__ ei, const int* __restrict__ ea,
                 int* __restrict__ cursor, unsigned* __restrict__ elist) {
    int e = blockIdx.x * blockDim.x + threadIdx.x;
    if (e >= N_EDGES) return;
    int src = ei[e];
    int dst = ei[N_EDGES + e];
    unsigned a0 = (unsigned)ea[2 * e];
    unsigned a1 = (unsigned)ea[2 * e + 1];
    int pos = atomicAdd(&cursor[dst], 1);
    elist[pos] = (unsigned)src | (a0 << 16) | (a1 << 19);
}

// ---------------- gather aggregation (one warp per node) ----------------
__global__ __launch_bounds__(256)
void agg_kernel(const float4* __restrict__ h,
                const int* __restrict__ rowptr,
                const unsigned* __restrict__ elist,
                const float4* __restrict__ e1l,   // [6,128]
                const float4* __restrict__ e2l,   // [4,128]
                float4* __restrict__ agg) {
    __shared__ float4 sEE[24 * 32];   // 24 (a0,a1) combos x 128 feats
    int tid = threadIdx.x;
    for (int i = tid; i < 24 * 32; i += 256) {
        int combo = i >> 5, lane = i & 31;
        int a0 = combo >> 2, a1 = combo & 3;
        float4 v1 = e1l[a0 * 32 + lane];
        float4 v2 = e2l[a1 * 32 + lane];
        float4 o;
        o.x = v1.x + v2.x; o.y = v1.y + v2.y;
        o.z = v1.z + v2.z; o.w = v1.w + v2.w;
        sEE[i] = o;
    }
    __syncthreads();

    int t = blockIdx.x * blockDim.x + tid;
    int n = t >> 5, lane = t & 31;
    if (n >= N_NODES) return;
    int beg = rowptr[n], end = rowptr[n + 1];
    float4 acc = make_float4(0.f, 0.f, 0.f, 0.f);
    for (int e = beg; e < end; e++) {
        unsigned p = elist[e];
        int src = (int)(p & 0xFFFFu);
        int combo = (int)(((p >> 16) & 7u) * 4u + ((p >> 19) & 3u));
        float4 v  = h[src * 32 + lane];
        float4 ee = sEE[combo * 32 + lane];
        acc.x += v.x + ee.x; acc.y += v.y + ee.y;
        acc.z += v.z + ee.z; acc.w += v.w + ee.w;
    }
    agg[n * 32 + lane] = acc;
}

// ---------------- f32x2 SGEMM: 128x128 tile, 8x8 microtile, BK=16 ----------
// C[M,N] = A[M,K] @ B[K,N] + bias, optional ReLU, optional BN stats.
template<int K, int N, bool RELU, bool STATS>
__global__ __launch_bounds__(256, 2)
void gemm128(const float* __restrict__ A, const float* __restrict__ B,
             const float* __restrict__ bias, float* __restrict__ C,
             int M, float* __restrict__ sums) {
    __shared__ float As[16][128];   // transposed: As[k][row]
    __shared__ float Bs[16][128];
    __shared__ float sS[128];
    __shared__ float sQ[128];

    const int tid = threadIdx.x;
    const int tx = tid & 15;        // column octet
    const int ty = tid >> 4;        // row octet
    const int row0 = blockIdx.x * 128;
    const int col0 = blockIdx.y * 128;

    if (STATS && tid < 128) { sS[tid] = 0.f; sQ[tid] = 0.f; }

    // A tile load mapping: 128 rows x 16 k, each thread 2 float4 (same row set)
    const int ar = tid & 127;          // row within tile
    const int ac = (tid >> 7) * 8;     // k offset: 0 or 8
    const bool arow_ok = (row0 + ar) < M;

    unsigned long long acc[8][4];
#pragma unroll
    for (int m = 0; m < 8; m++)
#pragma unroll
        for (int n = 0; n < 4; n++) acc[m][n] = 0ull;

    for (int k0 = 0; k0 < K; k0 += 16) {
        // load A (guarded) transposed into As
        float4 av0 = make_float4(0.f, 0.f, 0.f, 0.f), av1 = av0;
        if (arow_ok) {
            const float* ap = A + (size_t)(row0 + ar) * K + k0 + ac;
            av0 = *(const float4*)ap;
            av1 = *(const float4*)(ap + 4);
        }
        As[ac + 0][ar] = av0.x; As[ac + 1][ar] = av0.y;
        As[ac + 2][ar] = av0.z; As[ac + 3][ar] = av0.w;
        As[ac + 4][ar] = av1.x; As[ac + 5][ar] = av1.y;
        As[ac + 6][ar] = av1.z; As[ac + 7][ar] = av1.w;
        // load B: 16 x 128 floats = 512 float4, 2 per thread
#pragma unroll
        for (int r = 0; r < 2; r++) {
            int idx = tid + r * 256;
            int bk = idx >> 5;
            int bc = (idx & 31) * 4;
            *(float4*)&Bs[bk][bc] = *(const float4*)(B + (size_t)(k0 + bk) * N + col0 + bc);
        }
        __syncthreads();

#pragma unroll
        for (int k = 0; k < 16; k++) {
            float4 a0 = *(const float4*)&As[k][ty * 8];
            float4 a1 = *(const float4*)&As[k][ty * 8 + 4];
            // B pairs read directly as 64-bit lanes (consecutive cols)
            const unsigned long long* bp = (const unsigned long long*)&Bs[k][tx * 8];
            unsigned long long b0 = bp[0], b1 = bp[1], b2 = bp[2], b3 = bp[3];
            float av[8] = {a0.x, a0.y, a0.z, a0.w, a1.x, a1.y, a1.z, a1.w};
#pragma unroll
            for (int m = 0; m < 8; m++) {
                unsigned long long am = pack2_dup(av[m]);
                acc[m][0] = fma2(am, b0, acc[m][0]);
                acc[m][1] = fma2(am, b1, acc[m][1]);
                acc[m][2] = fma2(am, b2, acc[m][2]);
                acc[m][3] = fma2(am, b3, acc[m][3]);
            }
        }
        __syncthreads();
    }

    // epilogue
    float bv[8];
#pragma unroll
    for (int n = 0; n < 8; n++) bv[n] = bias[col0 + tx * 8 + n];

    float colS[8] = {}, colQ[8] = {};
#pragma unroll
    for (int m = 0; m < 8; m++) {
        int r = row0 + ty * 8 + m;
        float c[8];
#pragma unroll
        for (int n = 0; n < 4; n++) unpack2(acc[m][n], c[2 * n], c[2 * n + 1]);
        if (r < M) {
#pragma unroll
            for (int n = 0; n < 8; n++) {
                c[n] += bv[n];
                if (RELU) c[n] = fmaxf(c[n], 0.f);
                if (STATS) { colS[n] += c[n]; colQ[n] += c[n] * c[n]; }
            }
            float* cp = C + (size_t)r * N + col0 + tx * 8;
            *(float4*)cp       = make_float4(c[0], c[1], c[2], c[3]);
            *(float4*)(cp + 4) = make_float4(c[4], c[5], c[6], c[7]);
        }
    }

    if (STATS) {
#pragma unroll
        for (int n = 0; n < 8; n++) {
            atomicAdd(&sS[tx * 8 + n], colS[n]);
            atomicAdd(&sQ[tx * 8 + n], colQ[n]);
        }
        __syncthreads();
        if (tid < 128) {
            atomicAdd(&sums[col0 + tid], sS[tid]);
            atomicAdd(&sums[EMB + col0 + tid], sQ[tid]);
        }
    }
}

// ---------------- BN ----------------
__global__ void zero_sums(float* __restrict__ sums) {
    int t = threadIdx.x;
    if (t < 2 * EMB) sums[t] = 0.f;
}

__global__ void bn_prep(const float* __restrict__ sums,
                        const float* __restrict__ gamma,
                        const float* __restrict__ beta,
                        float* __restrict__ scale,
                        float* __restrict__ shift) {
    int c = threadIdx.x;
    if (c >= EMB) return;
    const float inv_n = 1.0f / (float)N_NODES;
    float mu  = sums[c] * inv_n;
    float var = sums[EMB + c] * inv_n - mu * mu;
    float rs  = rsqrtf(var + BN_EPS);
    float sc  = gamma[c] * rs;
    scale[c] = sc;
    shift[c] = beta[c] - mu * sc;
}

__global__ __launch_bounds__(256)
void bn_apply(const float4* __restrict__ h2, float4* __restrict__ out,
              const float4* __restrict__ scale, const float4* __restrict__ shift,
              int relu) {
    int t = blockIdx.x * blockDim.x + threadIdx.x;
    if (t >= N_NODES * 32) return;
    int lane = t & 31;
    float4 v  = h2[t];
    float4 sc = scale[lane];
    float4 sh = shift[lane];
    float4 o;
    o.x = fmaf(v.x, sc.x, sh.x);
    o.y = fmaf(v.y, sc.y, sh.y);
    o.z = fmaf(v.z, sc.z, sh.z);
    o.w = fmaf(v.w, sc.w, sh.w);
    if (relu) {
        o.x = fmaxf(o.x, 0.f); o.y = fmaxf(o.y, 0.f);
        o.z = fmaxf(o.z, 0.f); o.w = fmaxf(o.w, 0.f);
    }
    out[t] = o;
}

// ---------------- launch ----------------
extern "C" void kernel_launch(void* const* d_in, const int* in_sizes, int n_in,
                              void* d_out, int out_size) {
    const int*   x    = (const int*)  d_in[0];
    const int*   ei   = (const int*)  d_in[1];
    const int*   ea   = (const int*)  d_in[2];
    const float* atom = (const float*)d_in[3];
    const float* chir = (const float*)d_in[4];
    const float* hyb  = (const float*)d_in[5];
    const float* e1   = (const float*)d_in[6];
    const float* e2   = (const float*)d_in[7];
    const float* W1   = (const float*)d_in[8];
    const float* b1   = (const float*)d_in[9];
    const float* W2   = (const float*)d_in[10];
    const float* b2   = (const float*)d_in[11];
    const float* gamma= (const float*)d_in[12];
    const float* beta = (const float*)d_in[13];
    float* out = (float*)d_out;

    float *h, *agg, *hidden, *h2, *sums, *scale, *shift;
    int *counts, *cursor, *rowptr;
    unsigned* elist;
    cudaGetSymbolAddress((void**)&h,      g_h);
    cudaGetSymbolAddress((void**)&agg,    g_agg);
    cudaGetSymbolAddress((void**)&hidden, g_hidden);
    cudaGetSymbolAddress((void**)&h2,     g_h2);
    cudaGetSymbolAddress((void**)&sums,   g_sums);
    cudaGetSymbolAddress((void**)&scale,  g_scale);
    cudaGetSymbolAddress((void**)&shift,  g_shift);
    cudaGetSymbolAddress((void**)&counts, g_counts);
    cudaGetSymbolAddress((void**)&cursor, g_cursor);
    cudaGetSymbolAddress((void**)&rowptr, g_rowptr);
    cudaGetSymbolAddress((void**)&elist,  g_elist);

    const int tpb = 256;
    const int node_grid = (N_NODES * 32) / tpb;              // 6250
    const int edge_grid = (N_EDGES + tpb - 1) / tpb;         // 2344
    const int cnt_grid  = (N_NODES + tpb - 1) / tpb;         // 196
    const dim3 g1((N_NODES + 127) / 128, 2);                 // GEMM1 (391,2)
    const dim3 g2((N_NODES + 127) / 128, 1);                 // GEMM2 (391,1)

    // CSR build (edges are identical across layers)
    zero_counts<<<cnt_grid, tpb>>>(counts);
    hist_kernel<<<edge_grid, tpb>>>(ei, counts);
    scan_kernel<<<1, 1024>>>(counts, rowptr, cursor);
    fill_kernel<<<edge_grid, tpb>>>(ei, ea, cursor, elist);

    embed_kernel<<<node_grid, tpb>>>(x, (const float4*)atom, (const float4*)chir,
                                     (const float4*)hyb, (float4*)h);

    for (int l = 0; l < NLAYER; l++) {
        agg_kernel<<<node_grid, tpb>>>((const float4*)h, rowptr, elist,
                                       (const float4*)(e1 + (size_t)l * 6 * EMB),
                                       (const float4*)(e2 + (size_t)l * 4 * EMB),
                                       (float4*)agg);
        gemm128<128, 256, true,  false><<<g1, tpb>>>(agg, W1 + (size_t)l * 128 * 256,
                                                     b1 + (size_t)l * 256, hidden,
                                                     N_NODES, nullptr);
        zero_sums<<<1, 256>>>(sums);
        gemm128<256, 128, false, true ><<<g2, tpb>>>(hidden, W2 + (size_t)l * 256 * 128,
                                                     b2 + (size_t)l * 128, h2,
                                                     N_NODES, sums);
        bn_prep<<<1, 128>>>(sums, gamma + (size_t)l * EMB, beta + (size_t)l * EMB,
                            scale, shift);
        bn_apply<<<node_grid, tpb>>>((const float4*)h2,
                                     (l == NLAYER - 1) ? (float4*)out : (float4*)h,
                                     (const float4*)scale, (const float4*)shift,
                                     (l < NLAYER - 1) ? 1 : 0);
    }
}